// round 1
// baseline (speedup 1.0000x reference)
#include <cuda_runtime.h>
#include <math.h>

#define BTd 4
#define Ld 512
#define F1Dd 46
#define F2Dd 44
#define Cd 32
#define Kd 64
#define NBLKd 4
#define PWSTRIDE 109   // F2D + 2C + 1

// Scratch (device globals: no allocation allowed)
__device__ float g_x[BTd * Cd * Ld];
__device__ float g_y[BTd * Cd * Ld];
__device__ float g_eL[BTd * Ld * Kd];
__device__ float g_eR[BTd * Ld * Kd];
__device__ float g_pe[Ld * 32];   // pe_half: [l][0:16]=sin, [16:32]=cos
__device__ float g_sep[Ld];       // log(d+1), d = |i-j|

// ---------------------------------------------------------------------------
// init: sep table + positional-encoding half table
// ---------------------------------------------------------------------------
__global__ void k_init() {
    int l = threadIdx.x;
    g_sep[l] = logf((float)l + 1.0f);
    const float c0 = -logf(10000.0f) / 32.0f;  // half = K/2 = 32
    #pragma unroll
    for (int m = 0; m < 16; ++m) {
        float div = expf((2.0f * m) * c0);
        float a = (float)l * div;
        g_pe[l * 32 + m]      = sinf(a);
        g_pe[l * 32 + 16 + m] = cosf(a);
    }
}

// ---------------------------------------------------------------------------
// proj1d: x[bt][c][l] = b[c] + sum_f w[c][f] * t1d[bt][l][f]
// grid (C, BT), 512 threads (one per l)
// ---------------------------------------------------------------------------
__global__ void k_proj(const float* __restrict__ t1d,
                       const float* __restrict__ w,
                       const float* __restrict__ b) {
    int c = blockIdx.x, bt = blockIdx.y, l = threadIdx.x;
    __shared__ float sw[F1Dd];
    if (l < F1Dd) sw[l] = w[c * F1Dd + l];
    __syncthreads();
    const float* row = t1d + ((size_t)(bt * Ld + l)) * F1Dd;
    float acc = b[c];
    #pragma unroll
    for (int f = 0; f < F1Dd; ++f) acc += sw[f] * row[f];
    g_x[(bt * Cd + c) * Ld + l] = acc;
}

// ---------------------------------------------------------------------------
// block reduce: sum of (a, b) broadcast to all 512 threads
// ---------------------------------------------------------------------------
__device__ __forceinline__ float2 blockReduce2(float a, float b) {
    __shared__ float sa[16], sb[16], res[2];
    #pragma unroll
    for (int off = 16; off > 0; off >>= 1) {
        a += __shfl_down_sync(0xffffffffu, a, off);
        b += __shfl_down_sync(0xffffffffu, b, off);
    }
    int wid = threadIdx.x >> 5, lid = threadIdx.x & 31;
    if (lid == 0) { sa[wid] = a; sb[wid] = b; }
    __syncthreads();
    if (threadIdx.x == 0) {
        float ta = 0.f, tb = 0.f;
        #pragma unroll
        for (int i = 0; i < 16; ++i) { ta += sa[i]; tb += sb[i]; }
        res[0] = ta; res[1] = tb;
    }
    __syncthreads();
    return make_float2(res[0], res[1]);
}

__device__ __forceinline__ float conv_row(const float* __restrict__ xb,
                                          const float* __restrict__ sw, int l) {
    float acc = 0.f;
    #pragma unroll 4
    for (int ci = 0; ci < Cd; ++ci) {
        const float* xr = xb + ci * Ld;
        float xm = (l > 0)      ? xr[l - 1] : 0.f;
        float x0 = xr[l];
        float xp = (l < Ld - 1) ? xr[l + 1] : 0.f;
        acc += sw[ci * 3 + 0] * xm + sw[ci * 3 + 1] * x0 + sw[ci * 3 + 2] * xp;
    }
    return acc;
}

// conv + instance_norm + elu : g_x -> g_y       grid (C, BT), 512 threads
__global__ void k_convA(const float* __restrict__ cw, int blk) {
    int co = blockIdx.x, bt = blockIdx.y, l = threadIdx.x;
    __shared__ float sw[Cd * 3];
    if (l < Cd * 3) sw[l] = cw[((size_t)(blk * Cd + co)) * Cd * 3 + l];
    __syncthreads();
    float acc = conv_row(g_x + bt * Cd * Ld, sw, l);
    float2 s = blockReduce2(acc, acc * acc);
    float m = s.x * (1.0f / Ld);
    float var = s.y * (1.0f / Ld) - m * m;
    float v = (acc - m) * rsqrtf(var + 1e-5f);
    g_y[(bt * Cd + co) * Ld + l] = (v > 0.f) ? v : expm1f(v);
}

// conv + instance_norm + residual elu : g_y -> g_x     grid (C, BT), 512 thr
__global__ void k_convB(const float* __restrict__ cw, int blk) {
    int co = blockIdx.x, bt = blockIdx.y, l = threadIdx.x;
    __shared__ float sw[Cd * 3];
    if (l < Cd * 3) sw[l] = cw[((size_t)(blk * Cd + co)) * Cd * 3 + l];
    __syncthreads();
    float acc = conv_row(g_y + bt * Cd * Ld, sw, l);
    float2 s = blockReduce2(acc, acc * acc);
    float m = s.x * (1.0f / Ld);
    float var = s.y * (1.0f / Ld) - m * m;
    float v = (acc - m) * rsqrtf(var + 1e-5f);
    int idx = (bt * Cd + co) * Ld + l;
    float xo = g_x[idx] + v;
    g_x[idx] = (xo > 0.f) ? xo : expm1f(xo);
}

// ---------------------------------------------------------------------------
// eL[bt][l][o] = pb[o] + sum_c x[bt][c][l] * Wl[o][c]   (bias folded in)
// eR[bt][l][o] =         sum_c x[bt][c][l] * Wr[o][c]
// grid (L/8, BT), 512 threads = 8 l x 64 o
// ---------------------------------------------------------------------------
__global__ void k_eLR(const float* __restrict__ pw, const float* __restrict__ pb) {
    int bt = blockIdx.y;
    int l = blockIdx.x * 8 + (threadIdx.x >> 6);
    int o = threadIdx.x & 63;
    const float* wl = pw + o * PWSTRIDE + F2Dd;
    const float* wr = wl + Cd;
    float aL = pb[o], aR = 0.f;
    #pragma unroll
    for (int c = 0; c < Cd; ++c) {
        float e = g_x[(bt * Cd + c) * Ld + l];
        aL += wl[c] * e;
        aR += wr[c] * e;
    }
    g_eL[((size_t)(bt * Ld + l)) * Kd + o] = aL;
    g_eR[((size_t)(bt * Ld + l)) * Kd + o] = aR;
}

// ---------------------------------------------------------------------------
// pair kernel: out[row][o], row=(bt,i,j).  CTA: 128 rows (one i, j-tile 128).
// 256 threads = 32 row-groups (4 rows each) x 8 o-groups (o = og + 8*oo).
// ---------------------------------------------------------------------------
#define RTILE 128
#define TPAD 45

__global__ __launch_bounds__(256) void k_pair(const float* __restrict__ t2d,
                                              const float* __restrict__ pw,
                                              float* __restrict__ out) {
    __shared__ float sT[RTILE * TPAD];   // 23040 B, padded for bank-conflict-free
    __shared__ float sW[F2Dd * Kd];      // 11264 B, W2d transposed [k][o]
    __shared__ float sEL[Kd], sWsep[Kd], sPEi[32], sSep[RTILE];

    const int tid = threadIdx.x;
    const int bidx = blockIdx.x;            // 8192 blocks
    const int bt = bidx >> 11;              // 2048 blocks per bt
    const int i  = (bidx >> 2) & 511;
    const int j0 = (bidx & 3) << 7;
    const size_t rowbase = ((size_t)(bt * Ld + i)) * Ld + j0;

    // stage t2d tile (coalesced)
    {
        const float* src = t2d + rowbase * F2Dd;
        for (int idx = tid; idx < RTILE * F2Dd; idx += 256) {
            int r = idx / F2Dd, k = idx - r * F2Dd;
            sT[r * TPAD + k] = src[idx];
        }
    }
    // stage W2d transposed: sW[k*64 + o] = pw[o*109 + k]
    for (int idx = tid; idx < F2Dd * Kd; idx += 256) {
        int k = idx >> 6, o = idx & 63;
        sW[idx] = pw[o * PWSTRIDE + k];
    }
    if (tid < Kd) {
        sEL[tid]   = g_eL[((size_t)(bt * Ld + i)) * Kd + tid];
        sWsep[tid] = pw[tid * PWSTRIDE + (PWSTRIDE - 1)];
    }
    if (tid < 32) sPEi[tid] = g_pe[i * 32 + tid];
    if (tid < RTILE) { int j = j0 + tid; sSep[tid] = g_sep[abs(i - j)]; }
    __syncthreads();

    const int og = tid & 7;
    const int rg = tid >> 3;          // 0..31, 4 rows each
    const float* aT = sT + rg * 4 * TPAD;

    float acc[4][8];
    #pragma unroll
    for (int rr = 0; rr < 4; ++rr)
        #pragma unroll
        for (int oo = 0; oo < 8; ++oo) acc[rr][oo] = 0.f;

    #pragma unroll 4
    for (int k = 0; k < F2Dd; ++k) {
        float w[8];
        #pragma unroll
        for (int oo = 0; oo < 8; ++oo) w[oo] = sW[k * Kd + og + 8 * oo];
        #pragma unroll
        for (int rr = 0; rr < 4; ++rr) {
            float a = aT[rr * TPAD + k];
            #pragma unroll
            for (int oo = 0; oo < 8; ++oo) acc[rr][oo] += a * w[oo];
        }
    }

    // epilogue
    const int jloc0 = rg * 4;
    #pragma unroll
    for (int rr = 0; rr < 4; ++rr) {
        const int j = j0 + jloc0 + rr;
        const float sep = sSep[jloc0 + rr];
        const float* eRp = g_eR + ((size_t)(bt * Ld + j)) * Kd;
        const float* peJ = g_pe + j * 32;
        float* op = out + (rowbase + jloc0 + rr) * Kd;
        #pragma unroll
        for (int oo = 0; oo < 8; ++oo) {
            const int o = og + 8 * oo;
            float v = acc[rr][oo] + sEL[o] + eRp[o] + sep * sWsep[o];
            if (bt == 0) v += (oo < 4) ? sPEi[o] : peJ[o - 32];
            op[o] = v;
        }
    }
}

// ---------------------------------------------------------------------------
extern "C" void kernel_launch(void* const* d_in, const int* in_sizes, int n_in,
                              void* d_out, int out_size) {
    const float* t1d = (const float*)d_in[0];
    const float* t2d = (const float*)d_in[1];
    const float* p1w = (const float*)d_in[2];
    const float* p1b = (const float*)d_in[3];
    const float* c1w = (const float*)d_in[4];
    const float* c2w = (const float*)d_in[5];
    const float* pw  = (const float*)d_in[6];
    const float* pb  = (const float*)d_in[7];
    float* out = (float*)d_out;
    (void)in_sizes; (void)n_in; (void)out_size;

    k_init<<<1, 512>>>();
    k_proj<<<dim3(Cd, BTd), 512>>>(t1d, p1w, p1b);
    for (int i = 0; i < NBLKd; ++i) {
        k_convA<<<dim3(Cd, BTd), 512>>>(c1w, i);
        k_convB<<<dim3(Cd, BTd), 512>>>(c2w, i);
    }
    k_eLR<<<dim3(Ld / 8, BTd), 512>>>(pw, pb);
    k_pair<<<8192, 256>>>(t2d, pw, out);
}